// round 2
// baseline (speedup 1.0000x reference)
#include <cuda_runtime.h>
#include <cstdint>

#define B_ 8
#define N_ 2048
#define F_ 128
#define BK 16

// Scratch (device globals; no allocations allowed)
__device__ float g_dinv[B_ * N_];            // 64 KB
__device__ float g_y[B_ * N_ * F_];          // 8 MB

// ---------------- packed f32x2 helpers (Blackwell) ----------------
__device__ __forceinline__ unsigned long long pack2(float lo, float hi) {
    unsigned long long r;
    asm("mov.b64 %0, {%1, %2};" : "=l"(r) : "f"(lo), "f"(hi));
    return r;
}
__device__ __forceinline__ void unpack2(unsigned long long v, float& lo, float& hi) {
    asm("mov.b64 {%0, %1}, %2;" : "=f"(lo), "=f"(hi) : "l"(v));
}
__device__ __forceinline__ void fma2(unsigned long long& d, unsigned long long a,
                                     unsigned long long b) {
    asm("fma.rn.f32x2 %0, %1, %2, %0;" : "+l"(d) : "l"(a), "l"(b));
}

// ---------------- K1: row sums -> dinv ----------------
// One block per (b, n) row; 256 threads reduce 2048 floats.
__global__ __launch_bounds__(256) void rowsum_kernel(const float* __restrict__ adj) {
    int row = blockIdx.x;  // 0 .. B*N-1
    const float4* rp = reinterpret_cast<const float4*>(adj + (size_t)row * N_);
    int t = threadIdx.x;
    float s = 0.f;
#pragma unroll
    for (int i = 0; i < (N_ / 4) / 256; ++i) {  // 2 iters
        float4 v = rp[t + i * 256];
        s += (v.x + v.y) + (v.z + v.w);
    }
#pragma unroll
    for (int off = 16; off > 0; off >>= 1) s += __shfl_xor_sync(0xffffffffu, s, off);
    __shared__ float ws[8];
    if ((t & 31) == 0) ws[t >> 5] = s;
    __syncthreads();
    if (t < 8) {
        float v = ws[t];
#pragma unroll
        for (int off = 4; off > 0; off >>= 1) v += __shfl_xor_sync(0xffu, v, off);
        if (t == 0) g_dinv[row] = rsqrtf(v + 1.0f);  // +1 for self-loop
    }
}

// ---------------- K2: y = dinv .* (x @ W^T) ----------------
// M=16384 rows (b*N+m), N=128 outputs, K=128. 128x128 tile, BK=16, 8x8/thread.
__global__ __launch_bounds__(256) void xw_kernel(const float* __restrict__ x,
                                                 const float* __restrict__ W) {
    __shared__ float As[128][BK + 1];
    __shared__ float Bs[BK][128];
    const int rowBase = blockIdx.x * 128;
    const int tid = threadIdx.x;
    const int tx = tid & 15, ty = tid >> 4;
    const int m0 = ty * 8, n0 = tx * 8;

    unsigned long long acc[8][4];
#pragma unroll
    for (int i = 0; i < 8; ++i)
#pragma unroll
        for (int j = 0; j < 4; ++j) acc[i][j] = 0ull;

    for (int kb = 0; kb < F_; kb += BK) {
        // x tile: rows rowBase..+127, cols kb..kb+15
        {
            int l = tid * 4;
            int r0 = l >> 4, kk = l & 15;
#pragma unroll
            for (int c = 0; c < 2; ++c) {
                int r = r0 + c * 64;
                float4 v = *reinterpret_cast<const float4*>(
                    x + (size_t)(rowBase + r) * F_ + kb + kk);
                As[r][kk + 0] = v.x; As[r][kk + 1] = v.y;
                As[r][kk + 2] = v.z; As[r][kk + 3] = v.w;
            }
        }
        // W tile transposed: Bs[kk][o] = W[o][kb+kk]
        {
#pragma unroll
            for (int c = 0; c < 2; ++c) {
                int q = tid + c * 256;
                int o = q >> 2, kk4 = (q & 3) * 4;
                float4 v = *reinterpret_cast<const float4*>(W + (size_t)o * F_ + kb + kk4);
                Bs[kk4 + 0][o] = v.x; Bs[kk4 + 1][o] = v.y;
                Bs[kk4 + 2][o] = v.z; Bs[kk4 + 3][o] = v.w;
            }
        }
        __syncthreads();
#pragma unroll
        for (int kk = 0; kk < BK; ++kk) {
            float4 b0 = *reinterpret_cast<const float4*>(&Bs[kk][n0]);
            float4 b1 = *reinterpret_cast<const float4*>(&Bs[kk][n0 + 4]);
            unsigned long long bb[4] = {pack2(b0.x, b0.y), pack2(b0.z, b0.w),
                                        pack2(b1.x, b1.y), pack2(b1.z, b1.w)};
#pragma unroll
            for (int i = 0; i < 8; ++i) {
                float a = As[m0 + i][kk];
                unsigned long long aa = pack2(a, a);
#pragma unroll
                for (int j = 0; j < 4; ++j) fma2(acc[i][j], aa, bb[j]);
            }
        }
        __syncthreads();
    }
#pragma unroll
    for (int i = 0; i < 8; ++i) {
        int r = rowBase + m0 + i;
        float di = g_dinv[r];
        float o[8];
        unpack2(acc[i][0], o[0], o[1]);
        unpack2(acc[i][1], o[2], o[3]);
        unpack2(acc[i][2], o[4], o[5]);
        unpack2(acc[i][3], o[6], o[7]);
#pragma unroll
        for (int j = 0; j < 8; ++j) o[j] *= di;
        float* yp = g_y + (size_t)r * F_ + n0;
        *reinterpret_cast<float4*>(yp) = make_float4(o[0], o[1], o[2], o[3]);
        *reinterpret_cast<float4*>(yp + 4) = make_float4(o[4], o[5], o[6], o[7]);
    }
}

// ---------------- K3: out = dinv .* (adj @ y + y_self) + bias ----------------
// Per batch: M=2048, N=128, K=2048. 128x128 tile, BK=16, 8x8/thread.
__global__ __launch_bounds__(256) void spmm_kernel(const float* __restrict__ adj,
                                                   const float* __restrict__ bias,
                                                   float* __restrict__ out) {
    __shared__ float As[128][BK + 1];
    __shared__ float Bs[BK][128];
    const int b = blockIdx.y;
    const int rowBase = blockIdx.x * 128;
    const float* A = adj + (size_t)b * N_ * N_;
    const float* Y = g_y + (size_t)b * N_ * F_;
    const int tid = threadIdx.x;
    const int tx = tid & 15, ty = tid >> 4;
    const int m0 = ty * 8, n0 = tx * 8;

    unsigned long long acc[8][4];
#pragma unroll
    for (int i = 0; i < 8; ++i)
#pragma unroll
        for (int j = 0; j < 4; ++j) acc[i][j] = 0ull;

    for (int kb = 0; kb < N_; kb += BK) {
        // adj tile: rows rowBase..+127 (stride N_), cols kb..kb+15
        {
            int l = tid * 4;
            int r0 = l >> 4, kk = l & 15;
#pragma unroll
            for (int c = 0; c < 2; ++c) {
                int r = r0 + c * 64;
                float4 v = *reinterpret_cast<const float4*>(
                    A + (size_t)(rowBase + r) * N_ + kb + kk);
                As[r][kk + 0] = v.x; As[r][kk + 1] = v.y;
                As[r][kk + 2] = v.z; As[r][kk + 3] = v.w;
            }
        }
        // y tile: Bs[kk][f] = Y[(kb+kk)*F_ + f]
        {
#pragma unroll
            for (int c = 0; c < 2; ++c) {
                int q = tid + c * 256;
                int rr = q >> 5, col4 = (q & 31) * 4;
                float4 v = *reinterpret_cast<const float4*>(Y + (size_t)(kb + rr) * F_ + col4);
                *reinterpret_cast<float4*>(&Bs[rr][col4]) = v;
            }
        }
        __syncthreads();
#pragma unroll
        for (int kk = 0; kk < BK; ++kk) {
            float4 b0 = *reinterpret_cast<const float4*>(&Bs[kk][n0]);
            float4 b1 = *reinterpret_cast<const float4*>(&Bs[kk][n0 + 4]);
            unsigned long long bb[4] = {pack2(b0.x, b0.y), pack2(b0.z, b0.w),
                                        pack2(b1.x, b1.y), pack2(b1.z, b1.w)};
#pragma unroll
            for (int i = 0; i < 8; ++i) {
                float a = As[m0 + i][kk];
                unsigned long long aa = pack2(a, a);
#pragma unroll
                for (int j = 0; j < 4; ++j) fma2(acc[i][j], aa, bb[j]);
            }
        }
        __syncthreads();
    }

    float bv[8];
    *reinterpret_cast<float4*>(&bv[0]) = *reinterpret_cast<const float4*>(bias + n0);
    *reinterpret_cast<float4*>(&bv[4]) = *reinterpret_cast<const float4*>(bias + n0 + 4);

#pragma unroll
    for (int i = 0; i < 8; ++i) {
        int gr = rowBase + m0 + i;  // row within batch
        float di = g_dinv[b * N_ + gr];
        const float* yrow = Y + (size_t)gr * F_ + n0;
        float4 y0 = *reinterpret_cast<const float4*>(yrow);
        float4 y1 = *reinterpret_cast<const float4*>(yrow + 4);
        float o[8];
        unpack2(acc[i][0], o[0], o[1]);
        unpack2(acc[i][1], o[2], o[3]);
        unpack2(acc[i][2], o[4], o[5]);
        unpack2(acc[i][3], o[6], o[7]);
        // self-loop contribution (+1 * y[n,:]) then row scale + bias
        o[0] = di * (o[0] + y0.x) + bv[0];
        o[1] = di * (o[1] + y0.y) + bv[1];
        o[2] = di * (o[2] + y0.z) + bv[2];
        o[3] = di * (o[3] + y0.w) + bv[3];
        o[4] = di * (o[4] + y1.x) + bv[4];
        o[5] = di * (o[5] + y1.y) + bv[5];
        o[6] = di * (o[6] + y1.z) + bv[6];
        o[7] = di * (o[7] + y1.w) + bv[7];
        float* op = out + ((size_t)b * N_ + gr) * F_ + n0;
        *reinterpret_cast<float4*>(op) = make_float4(o[0], o[1], o[2], o[3]);
        *reinterpret_cast<float4*>(op + 4) = make_float4(o[4], o[5], o[6], o[7]);
    }
}

extern "C" void kernel_launch(void* const* d_in, const int* in_sizes, int n_in,
                              void* d_out, int out_size) {
    const float* x = (const float*)d_in[0];    // [8,2048,128]
    const float* adj = (const float*)d_in[1];  // [8,2048,2048]
    const float* W = (const float*)d_in[2];    // [128,128]
    const float* bias = (const float*)d_in[3]; // [128]
    float* out = (float*)d_out;                // [8,2048,128]

    rowsum_kernel<<<B_ * N_, 256>>>(adj);
    xw_kernel<<<(B_ * N_) / 128, 256>>>(x, W);
    spmm_kernel<<<dim3(N_ / 128, B_), 256>>>(adj, bias, out);
}

// round 6
// speedup vs baseline: 2.2970x; 2.2970x over previous
#include <cuda_runtime.h>
#include <cuda_bf16.h>
#include <cstdint>

#define B_ 8
#define N_ 2048
#define F_ 128
#define BK 16

// ---------------- scratch (device globals; no allocs) ----------------
__device__ float g_dinv[B_ * N_];                     // 64 KB
__device__ float g_y[B_ * N_ * F_];                   // 8 MB fp32 [b][m][f]
__device__ __nv_bfloat16 g_yth[B_ * F_ * N_];         // 4 MB  [b][f][m] hi
__device__ __nv_bfloat16 g_ytl[B_ * F_ * N_];         // 4 MB  [b][f][m] lo

// ---------------- helpers ----------------
__device__ __forceinline__ uint32_t smem_u32(const void* p) {
    uint32_t a;
    asm("{ .reg .u64 t; cvta.to.shared.u64 t, %1; cvt.u32.u64 %0, t; }" : "=r"(a) : "l"(p));
    return a;
}
__device__ __forceinline__ void cp16(uint32_t dst, const void* src) {
    asm volatile("cp.async.cg.shared.global [%0], [%1], 16;" :: "r"(dst), "l"(src) : "memory");
}
__device__ __forceinline__ unsigned long long pack2(float lo, float hi) {
    unsigned long long r;
    asm("mov.b64 %0, {%1, %2};" : "=l"(r) : "f"(lo), "f"(hi));
    return r;
}
__device__ __forceinline__ void unpack2(unsigned long long v, float& lo, float& hi) {
    asm("mov.b64 {%0, %1}, %2;" : "=f"(lo), "=f"(hi) : "l"(v));
}
__device__ __forceinline__ void fma2(unsigned long long& d, unsigned long long a,
                                     unsigned long long b) {
    asm("fma.rn.f32x2 %0, %1, %2, %0;" : "+l"(d) : "l"(a), "l"(b));
}
// bf16 split: (a,b) -> hi bf16x2 word (low half = a), lo word
__device__ __forceinline__ void split_pair(float a, float b, uint32_t& hi, uint32_t& lo) {
    __nv_bfloat162 h = __floats2bfloat162_rn(a, b);
    float ra = __bfloat162float(h.x), rb = __bfloat162float(h.y);
    __nv_bfloat162 l = __floats2bfloat162_rn(a - ra, b - rb);
    hi = *reinterpret_cast<uint32_t*>(&h);
    lo = *reinterpret_cast<uint32_t*>(&l);
}
__device__ __forceinline__ void mma_bf16(float* c, const uint32_t* a, const uint32_t* bb) {
    asm volatile(
        "mma.sync.aligned.m16n8k16.row.col.f32.bf16.bf16.f32 "
        "{%0,%1,%2,%3}, {%4,%5,%6,%7}, {%8,%9}, {%0,%1,%2,%3};"
        : "+f"(c[0]), "+f"(c[1]), "+f"(c[2]), "+f"(c[3])
        : "r"(a[0]), "r"(a[1]), "r"(a[2]), "r"(a[3]), "r"(bb[0]), "r"(bb[1]));
}

// ---------------- K1: row sums -> dinv ----------------
__global__ __launch_bounds__(256) void rowsum_kernel(const float* __restrict__ adj) {
    int row = blockIdx.x;
    const float4* rp = reinterpret_cast<const float4*>(adj + (size_t)row * N_);
    int t = threadIdx.x;
    float s = 0.f;
#pragma unroll
    for (int i = 0; i < (N_ / 4) / 256; ++i) {
        float4 v = rp[t + i * 256];
        s += (v.x + v.y) + (v.z + v.w);
    }
#pragma unroll
    for (int off = 16; off > 0; off >>= 1) s += __shfl_xor_sync(0xffffffffu, s, off);
    __shared__ float ws[8];
    if ((t & 31) == 0) ws[t >> 5] = s;
    __syncthreads();
    if (t < 8) {
        float v = ws[t];
#pragma unroll
        for (int off = 4; off > 0; off >>= 1) v += __shfl_xor_sync(0xffu, v, off);
        if (t == 0) g_dinv[row] = rsqrtf(v + 1.0f);
    }
}

// ---------------- K2: y = dinv .* (x @ W^T); also write yT hi/lo bf16 ----------------
__global__ __launch_bounds__(256) void xw_kernel(const float* __restrict__ x,
                                                 const float* __restrict__ W) {
    __shared__ __align__(16) char sbuf[128 * 136 * 2];
    float (*As)[BK + 1] = reinterpret_cast<float (*)[BK + 1]>(sbuf);
    float (*Bs)[128] = reinterpret_cast<float (*)[128]>(sbuf + 128 * (BK + 1) * 4);
    unsigned short (*Tt)[136] = reinterpret_cast<unsigned short (*)[136]>(sbuf);

    const int rowBase = blockIdx.x * 128;
    const int tid = threadIdx.x;
    const int tx = tid & 15, ty = tid >> 4;
    const int m0 = ty * 8, n0 = tx * 8;

    unsigned long long acc[8][4];
#pragma unroll
    for (int i = 0; i < 8; ++i)
#pragma unroll
        for (int j = 0; j < 4; ++j) acc[i][j] = 0ull;

    for (int kb = 0; kb < F_; kb += BK) {
        {
            int l = tid * 4;
            int r0 = l >> 4, kk = l & 15;
#pragma unroll
            for (int c = 0; c < 2; ++c) {
                int r = r0 + c * 64;
                float4 v = *reinterpret_cast<const float4*>(
                    x + (size_t)(rowBase + r) * F_ + kb + kk);
                As[r][kk + 0] = v.x; As[r][kk + 1] = v.y;
                As[r][kk + 2] = v.z; As[r][kk + 3] = v.w;
            }
        }
        {
#pragma unroll
            for (int c = 0; c < 2; ++c) {
                int q = tid + c * 256;
                int o = q >> 2, kk4 = (q & 3) * 4;
                float4 v = *reinterpret_cast<const float4*>(W + (size_t)o * F_ + kb + kk4);
                Bs[kk4 + 0][o] = v.x; Bs[kk4 + 1][o] = v.y;
                Bs[kk4 + 2][o] = v.z; Bs[kk4 + 3][o] = v.w;
            }
        }
        __syncthreads();
#pragma unroll
        for (int kk = 0; kk < BK; ++kk) {
            float4 b0 = *reinterpret_cast<const float4*>(&Bs[kk][n0]);
            float4 b1 = *reinterpret_cast<const float4*>(&Bs[kk][n0 + 4]);
            unsigned long long bb[4] = {pack2(b0.x, b0.y), pack2(b0.z, b0.w),
                                        pack2(b1.x, b1.y), pack2(b1.z, b1.w)};
#pragma unroll
            for (int i = 0; i < 8; ++i) {
                float a = As[m0 + i][kk];
                unsigned long long aa = pack2(a, a);
#pragma unroll
                for (int j = 0; j < 4; ++j) fma2(acc[i][j], aa, bb[j]);
            }
        }
        __syncthreads();
    }

    float oa[8][8];
#pragma unroll
    for (int i = 0; i < 8; ++i) {
        int r = rowBase + m0 + i;
        float di = g_dinv[r];
        unpack2(acc[i][0], oa[i][0], oa[i][1]);
        unpack2(acc[i][1], oa[i][2], oa[i][3]);
        unpack2(acc[i][2], oa[i][4], oa[i][5]);
        unpack2(acc[i][3], oa[i][6], oa[i][7]);
#pragma unroll
        for (int j = 0; j < 8; ++j) oa[i][j] *= di;
        float* yp = g_y + (size_t)r * F_ + n0;
        *reinterpret_cast<float4*>(yp) = make_float4(oa[i][0], oa[i][1], oa[i][2], oa[i][3]);
        *reinterpret_cast<float4*>(yp + 4) = make_float4(oa[i][4], oa[i][5], oa[i][6], oa[i][7]);
    }

    const int b = rowBase / N_;
    const int mloc0 = rowBase % N_;
    // pass 1: hi
#pragma unroll
    for (int i = 0; i < 8; ++i)
#pragma unroll
        for (int j = 0; j < 8; ++j) {
            __nv_bfloat16 h = __float2bfloat16_rn(oa[i][j]);
            Tt[n0 + j][m0 + i] = *reinterpret_cast<unsigned short*>(&h);
        }
    __syncthreads();
    {
        int f = tid >> 1, half = tid & 1;
        const uint4* src = reinterpret_cast<const uint4*>(&Tt[f][half * 64]);
        uint4* dst = reinterpret_cast<uint4*>(
            g_yth + ((size_t)b * F_ + f) * N_ + mloc0 + half * 64);
#pragma unroll
        for (int q = 0; q < 8; ++q) dst[q] = src[q];
    }
    __syncthreads();
    // pass 2: lo
#pragma unroll
    for (int i = 0; i < 8; ++i)
#pragma unroll
        for (int j = 0; j < 8; ++j) {
            __nv_bfloat16 h = __float2bfloat16_rn(oa[i][j]);
            float resid = oa[i][j] - __bfloat162float(h);
            __nv_bfloat16 l = __float2bfloat16_rn(resid);
            Tt[n0 + j][m0 + i] = *reinterpret_cast<unsigned short*>(&l);
        }
    __syncthreads();
    {
        int f = tid >> 1, half = tid & 1;
        const uint4* src = reinterpret_cast<const uint4*>(&Tt[f][half * 64]);
        uint4* dst = reinterpret_cast<uint4*>(
            g_ytl + ((size_t)b * F_ + f) * N_ + mloc0 + half * 64);
#pragma unroll
        for (int q = 0; q < 8; ++q) dst[q] = src[q];
    }
}

// ---------------- K3: mma.sync bf16-split GEMM ----------------
// CTA: 128x128 tile, 8 warps (2x4), warp tile 64x32, KC=64, double-buffered.
// smem rows padded to 144 B -> conflict-free m16n8k16 fragment LDS.
#define KC 64
#define APAD 144
#define STG_AH 0
#define STG_AL 18432
#define STG_BH 36864
#define STG_BL 55296
#define STAGE_SZ 73728
#define K3_SMEM (2 * STAGE_SZ)

__global__ __launch_bounds__(256, 1) void spmm_mma(const float* __restrict__ adj,
                                                   const float* __restrict__ bias,
                                                   float* __restrict__ out) {
    extern __shared__ __align__(16) char smem[];
    const uint32_t sb = smem_u32(smem);
    const int tid = threadIdx.x;
    const int wid = tid >> 5, lane = tid & 31;
    const int g = lane >> 2, t = lane & 3;
    const int warpM = wid >> 2, warpC = wid & 3;
    const int b = blockIdx.y, rowBase = blockIdx.x * 128;

    const float* A = adj + (size_t)b * N_ * N_ + (size_t)rowBase * N_;
    const __nv_bfloat16* Yh = g_yth + (size_t)b * F_ * N_;
    const __nv_bfloat16* Yl = g_ytl + (size_t)b * F_ * N_;

    const int r0 = tid >> 4, c4 = tid & 15;   // A loader: rows r0+16j, float4 col c4
    const int bf0 = tid >> 3, bc16 = tid & 7; // B loader: rows bf0+32j, 16B col bc16

    float acc[4][4][4];
#pragma unroll
    for (int i = 0; i < 4; ++i)
#pragma unroll
        for (int j = 0; j < 4; ++j)
#pragma unroll
            for (int q = 0; q < 4; ++q) acc[i][j][q] = 0.f;

    float4 av[8];

    // ---- prologue: chunk 0 ----
#pragma unroll
    for (int j = 0; j < 8; ++j)
        av[j] = *reinterpret_cast<const float4*>(A + (size_t)(r0 + 16 * j) * N_ + c4 * 4);
#pragma unroll
    for (int j = 0; j < 4; ++j) {
        int f = bf0 + 32 * j;
        cp16(sb + STG_BH + f * APAD + bc16 * 16, Yh + (size_t)f * N_ + bc16 * 8);
        cp16(sb + STG_BL + f * APAD + bc16 * 16, Yl + (size_t)f * N_ + bc16 * 8);
    }
    asm volatile("cp.async.commit_group;" ::: "memory");
#pragma unroll
    for (int j = 0; j < 8; ++j) {
        uint32_t h0, l0, h1, l1;
        split_pair(av[j].x, av[j].y, h0, l0);
        split_pair(av[j].z, av[j].w, h1, l1);
        int r = r0 + 16 * j;
        *reinterpret_cast<uint2*>(smem + STG_AH + r * APAD + c4 * 8) = make_uint2(h0, h1);
        *reinterpret_cast<uint2*>(smem + STG_AL + r * APAD + c4 * 8) = make_uint2(l0, l1);
    }
    asm volatile("cp.async.wait_group 0;" ::: "memory");
    __syncthreads();

    // ---- main loop ----
    for (int it = 0; it < N_ / KC; ++it) {
        const int cur = it & 1;
        const char* stg = smem + cur * STAGE_SZ;

        if (it < N_ / KC - 1) {
            const int kb = (it + 1) * KC;
#pragma unroll
            for (int j = 0; j < 8; ++j)
                av[j] = *reinterpret_cast<const float4*>(
                    A + (size_t)(r0 + 16 * j) * N_ + kb + c4 * 4);
            const uint32_t nb = sb + (cur ^ 1) * STAGE_SZ;
#pragma unroll
            for (int j = 0; j < 4; ++j) {
                int f = bf0 + 32 * j;
                cp16(nb + STG_BH + f * APAD + bc16 * 16, Yh + (size_t)f * N_ + kb + bc16 * 8);
                cp16(nb + STG_BL + f * APAD + bc16 * 16, Yl + (size_t)f * N_ + kb + bc16 * 8);
            }
            asm volatile("cp.async.commit_group;" ::: "memory");
        }

        // MMA over current stage
#pragma unroll
        for (int k16 = 0; k16 < 4; ++k16) {
            const int koff = k16 * 32 + t * 4;
            uint32_t ah[4][4], al[4][4];
#pragma unroll
            for (int mt = 0; mt < 4; ++mt) {
                int rg = warpM * 64 + mt * 16 + g;
                const char* pH = stg + STG_AH + rg * APAD + koff;
                const char* pL = stg + STG_AL + rg * APAD + koff;
                ah[mt][0] = *reinterpret_cast<const uint32_t*>(pH);
                ah[mt][1] = *reinterpret_cast<const uint32_t*>(pH + 8 * APAD);
                ah[mt][2] = *reinterpret_cast<const uint32_t*>(pH + 16);
                ah[mt][3] = *reinterpret_cast<const uint32_t*>(pH + 8 * APAD + 16);
                al[mt][0] = *reinterpret_cast<const uint32_t*>(pL);
                al[mt][1] = *reinterpret_cast<const uint32_t*>(pL + 8 * APAD);
                al[mt][2] = *reinterpret_cast<const uint32_t*>(pL + 16);
                al[mt][3] = *reinterpret_cast<const uint32_t*>(pL + 8 * APAD + 16);
            }
            uint32_t bh2[4][2], bl2[4][2];
#pragma unroll
            for (int nt = 0; nt < 4; ++nt) {
                int f = warpC * 32 + nt * 8 + g;
                const char* pH = stg + STG_BH + f * APAD + koff;
                const char* pL = stg + STG_BL + f * APAD + koff;
                bh2[nt][0] = *reinterpret_cast<const uint32_t*>(pH);
                bh2[nt][1] = *reinterpret_cast<const uint32_t*>(pH + 16);
                bl2[nt][0] = *reinterpret_cast<const uint32_t*>(pL);
                bl2[nt][1] = *reinterpret_cast<const uint32_t*>(pL + 16);
            }
#pragma unroll
            for (int mt = 0; mt < 4; ++mt)
#pragma unroll
                for (int nt = 0; nt < 4; ++nt) {
                    mma_bf16(acc[mt][nt], ah[mt], bh2[nt]);
                    mma_bf16(acc[mt][nt], al[mt], bh2[nt]);
                    mma_bf16(acc[mt][nt], ah[mt], bl2[nt]);
                }
        }

        if (it < N_ / KC - 1) {
            char* nst = smem + (cur ^ 1) * STAGE_SZ;
#pragma unroll
            for (int j = 0; j < 8; ++j) {
                uint32_t h0, l0, h1, l1;
                split_pair(av[j].x, av[j].y, h0, l0);
                split_pair(av[j].z, av[j].w, h1, l1);
                int r = r0 + 16 * j;
                *reinterpret_cast<uint2*>(nst + STG_AH + r * APAD + c4 * 8) = make_uint2(h0, h1);
                *reinterpret_cast<uint2*>(nst + STG_AL + r * APAD + c4 * 8) = make_uint2(l0, l1);
            }
            asm volatile("cp.async.wait_group 0;" ::: "memory");
        }
        __syncthreads();
    }

    // ---- epilogue: dinv * (acc + y_self) + bias ----
    const float* Yrow = g_y + ((size_t)b * N_ + rowBase) * F_;
    float* Orow = out + ((size_t)b * N_ + rowBase) * F_;
    const float* dv = g_dinv + b * N_ + rowBase;
#pragma unroll
    for (int mt = 0; mt < 4; ++mt) {
        int rl0 = warpM * 64 + mt * 16 + g;
        int rl1 = rl0 + 8;
        float d0 = dv[rl0], d1 = dv[rl1];
#pragma unroll
        for (int nt = 0; nt < 4; ++nt) {
            int c = warpC * 32 + nt * 8 + 2 * t;
            float2 y0 = *reinterpret_cast<const float2*>(Yrow + (size_t)rl0 * F_ + c);
            float2 y1 = *reinterpret_cast<const float2*>(Yrow + (size_t)rl1 * F_ + c);
            float2 bv = *reinterpret_cast<const float2*>(bias + c);
            float2 o0, o1;
            o0.x = d0 * (acc[mt][nt][0] + y0.x) + bv.x;
            o0.y = d0 * (acc[mt][nt][1] + y0.y) + bv.y;
            o1.x = d1 * (acc[mt][nt][2] + y1.x) + bv.x;
            o1.y = d1 * (acc[mt][nt][3] + y1.y) + bv.y;
            *reinterpret_cast<float2*>(Orow + (size_t)rl0 * F_ + c) = o0;
            *reinterpret_cast<float2*>(Orow + (size_t)rl1 * F_ + c) = o1;
        }
    }
}

extern "C" void kernel_launch(void* const* d_in, const int* in_sizes, int n_in,
                              void* d_out, int out_size) {
    const float* x = (const float*)d_in[0];    // [8,2048,128]
    const float* adj = (const float*)d_in[1];  // [8,2048,2048]
    const float* W = (const float*)d_in[2];    // [128,128]
    const float* bias = (const float*)d_in[3]; // [128]
    float* out = (float*)d_out;                // [8,2048,128]

    cudaFuncSetAttribute(spmm_mma, cudaFuncAttributeMaxDynamicSharedMemorySize, K3_SMEM);

    rowsum_kernel<<<B_ * N_, 256>>>(adj);
    xw_kernel<<<(B_ * N_) / 128, 256>>>(x, W);
    spmm_mma<<<dim3(N_ / 128, B_), 256, K3_SMEM>>>(adj, bias, out);
}

// round 9
// speedup vs baseline: 3.4219x; 1.4897x over previous
#include <cuda_runtime.h>
#include <cuda_fp16.h>
#include <cstdint>

#define B_ 8
#define N_ 2048
#define F_ 128
#define BK 16

// ---------------- scratch (device globals; no allocs) ----------------
__device__ float g_dinv[B_ * N_];        // 64 KB
__device__ float g_y[B_ * N_ * F_];      // 8 MB fp32 [b][m][f]
__device__ __half g_yt[B_ * F_ * N_];    // 4 MB fp16 [b][f][m]

// ---------------- helpers ----------------
__device__ __forceinline__ uint32_t smem_u32(const void* p) {
    uint32_t a;
    asm("{ .reg .u64 t; cvta.to.shared.u64 t, %1; cvt.u32.u64 %0, t; }" : "=r"(a) : "l"(p));
    return a;
}
__device__ __forceinline__ void cp16(uint32_t dst, const void* src) {
    asm volatile("cp.async.cg.shared.global [%0], [%1], 16;" :: "r"(dst), "l"(src) : "memory");
}
__device__ __forceinline__ unsigned long long pack2(float lo, float hi) {
    unsigned long long r;
    asm("mov.b64 %0, {%1, %2};" : "=l"(r) : "f"(lo), "f"(hi));
    return r;
}
__device__ __forceinline__ void unpack2(unsigned long long v, float& lo, float& hi) {
    asm("mov.b64 {%0, %1}, %2;" : "=f"(lo), "=f"(hi) : "l"(v));
}
__device__ __forceinline__ void fma2(unsigned long long& d, unsigned long long a,
                                     unsigned long long b) {
    asm("fma.rn.f32x2 %0, %1, %2, %0;" : "+l"(d) : "l"(a), "l"(b));
}
__device__ __forceinline__ void mma_f16(float* c, const uint32_t* a, const uint32_t* bb) {
    asm volatile(
        "mma.sync.aligned.m16n8k16.row.col.f32.f16.f16.f32 "
        "{%0,%1,%2,%3}, {%4,%5,%6,%7}, {%8,%9}, {%0,%1,%2,%3};"
        : "+f"(c[0]), "+f"(c[1]), "+f"(c[2]), "+f"(c[3])
        : "r"(a[0]), "r"(a[1]), "r"(a[2]), "r"(a[3]), "r"(bb[0]), "r"(bb[1]));
}

// ---------------- K1: row sums -> dinv ----------------
__global__ __launch_bounds__(256) void rowsum_kernel(const float* __restrict__ adj) {
    int row = blockIdx.x;
    const float4* rp = reinterpret_cast<const float4*>(adj + (size_t)row * N_);
    int t = threadIdx.x;
    float s = 0.f;
#pragma unroll
    for (int i = 0; i < (N_ / 4) / 256; ++i) {
        float4 v = rp[t + i * 256];
        s += (v.x + v.y) + (v.z + v.w);
    }
#pragma unroll
    for (int off = 16; off > 0; off >>= 1) s += __shfl_xor_sync(0xffffffffu, s, off);
    __shared__ float ws[8];
    if ((t & 31) == 0) ws[t >> 5] = s;
    __syncthreads();
    if (t < 8) {
        float v = ws[t];
#pragma unroll
        for (int off = 4; off > 0; off >>= 1) v += __shfl_xor_sync(0xffu, v, off);
        if (t == 0) g_dinv[row] = rsqrtf(v + 1.0f);
    }
}

// ---------------- K2: y = dinv .* (x @ W^T); also write yT fp16 ----------------
__global__ __launch_bounds__(256) void xw_kernel(const float* __restrict__ x,
                                                 const float* __restrict__ W) {
    __shared__ __align__(16) char sbuf[128 * 136 * 2];
    float (*As)[BK + 1] = reinterpret_cast<float (*)[BK + 1]>(sbuf);
    float (*Bs)[128] = reinterpret_cast<float (*)[128]>(sbuf + 128 * (BK + 1) * 4);
    unsigned short (*Tt)[136] = reinterpret_cast<unsigned short (*)[136]>(sbuf);

    const int rowBase = blockIdx.x * 128;
    const int tid = threadIdx.x;
    const int tx = tid & 15, ty = tid >> 4;
    const int m0 = ty * 8, n0 = tx * 8;

    unsigned long long acc[8][4];
#pragma unroll
    for (int i = 0; i < 8; ++i)
#pragma unroll
        for (int j = 0; j < 4; ++j) acc[i][j] = 0ull;

    for (int kb = 0; kb < F_; kb += BK) {
        {
            int l = tid * 4;
            int r0 = l >> 4, kk = l & 15;
#pragma unroll
            for (int c = 0; c < 2; ++c) {
                int r = r0 + c * 64;
                float4 v = *reinterpret_cast<const float4*>(
                    x + (size_t)(rowBase + r) * F_ + kb + kk);
                As[r][kk + 0] = v.x; As[r][kk + 1] = v.y;
                As[r][kk + 2] = v.z; As[r][kk + 3] = v.w;
            }
        }
        {
#pragma unroll
            for (int c = 0; c < 2; ++c) {
                int q = tid + c * 256;
                int o = q >> 2, kk4 = (q & 3) * 4;
                float4 v = *reinterpret_cast<const float4*>(W + (size_t)o * F_ + kb + kk4);
                Bs[kk4 + 0][o] = v.x; Bs[kk4 + 1][o] = v.y;
                Bs[kk4 + 2][o] = v.z; Bs[kk4 + 3][o] = v.w;
            }
        }
        __syncthreads();
#pragma unroll
        for (int kk = 0; kk < BK; ++kk) {
            float4 b0 = *reinterpret_cast<const float4*>(&Bs[kk][n0]);
            float4 b1 = *reinterpret_cast<const float4*>(&Bs[kk][n0 + 4]);
            unsigned long long bb[4] = {pack2(b0.x, b0.y), pack2(b0.z, b0.w),
                                        pack2(b1.x, b1.y), pack2(b1.z, b1.w)};
#pragma unroll
            for (int i = 0; i < 8; ++i) {
                float a = As[m0 + i][kk];
                unsigned long long aa = pack2(a, a);
#pragma unroll
                for (int j = 0; j < 4; ++j) fma2(acc[i][j], aa, bb[j]);
            }
        }
        __syncthreads();
    }

    float oa[8][8];
#pragma unroll
    for (int i = 0; i < 8; ++i) {
        int r = rowBase + m0 + i;
        float di = g_dinv[r];
        unpack2(acc[i][0], oa[i][0], oa[i][1]);
        unpack2(acc[i][1], oa[i][2], oa[i][3]);
        unpack2(acc[i][2], oa[i][4], oa[i][5]);
        unpack2(acc[i][3], oa[i][6], oa[i][7]);
#pragma unroll
        for (int j = 0; j < 8; ++j) oa[i][j] *= di;
        float* yp = g_y + (size_t)r * F_ + n0;
        *reinterpret_cast<float4*>(yp) = make_float4(oa[i][0], oa[i][1], oa[i][2], oa[i][3]);
        *reinterpret_cast<float4*>(yp + 4) = make_float4(oa[i][4], oa[i][5], oa[i][6], oa[i][7]);
    }

    const int b = rowBase / N_;
    const int mloc0 = rowBase % N_;
    // single transpose pass: Tt[f][m] = fp16(y)
#pragma unroll
    for (int i = 0; i < 8; ++i)
#pragma unroll
        for (int j = 0; j < 8; ++j) {
            __half h = __float2half_rn(oa[i][j]);
            Tt[n0 + j][m0 + i] = *reinterpret_cast<unsigned short*>(&h);
        }
    __syncthreads();
    {
        int f = tid >> 1, half = tid & 1;
        const uint4* src = reinterpret_cast<const uint4*>(&Tt[f][half * 64]);
        uint4* dst = reinterpret_cast<uint4*>(
            g_yt + ((size_t)b * F_ + f) * N_ + mloc0 + half * 64);
#pragma unroll
        for (int q = 0; q < 8; ++q) dst[q] = src[q];
    }
}

// ---------------- K3: single-fp16 mma.sync GEMM ----------------
// CTA: 128x128 tile, 8 warps (2x4), warp tile 64x32, KC=64, double-buffered.
// smem rows padded to 144 B -> conflict-free fragment LDS.
#define KC 64
#define APAD 144
#define STG_A 0
#define STG_B 18432
#define STAGE_SZ 36864
#define K3_SMEM (2 * STAGE_SZ)

__global__ __launch_bounds__(256, 1) void spmm_mma(const float* __restrict__ adj,
                                                   const float* __restrict__ bias,
                                                   float* __restrict__ out) {
    extern __shared__ __align__(16) char smem[];
    const uint32_t sb = smem_u32(smem);
    const int tid = threadIdx.x;
    const int wid = tid >> 5, lane = tid & 31;
    const int g = lane >> 2, t = lane & 3;
    const int warpM = wid >> 2, warpC = wid & 3;
    const int b = blockIdx.y, rowBase = blockIdx.x * 128;

    const float* A = adj + (size_t)b * N_ * N_ + (size_t)rowBase * N_;
    const __half* Yt = g_yt + (size_t)b * F_ * N_;

    const int r0 = tid >> 4, c4 = tid & 15;   // A loader: rows r0+16j, float4 col c4
    const int bf0 = tid >> 3, bc16 = tid & 7; // B loader: rows bf0+32j, 16B col bc16

    float acc[4][4][4];
#pragma unroll
    for (int i = 0; i < 4; ++i)
#pragma unroll
        for (int j = 0; j < 4; ++j)
#pragma unroll
            for (int q = 0; q < 4; ++q) acc[i][j][q] = 0.f;

    float4 av[8];

    // ---- prologue: chunk 0 ----
#pragma unroll
    for (int j = 0; j < 8; ++j)
        av[j] = *reinterpret_cast<const float4*>(A + (size_t)(r0 + 16 * j) * N_ + c4 * 4);
#pragma unroll
    for (int j = 0; j < 4; ++j) {
        int f = bf0 + 32 * j;
        cp16(sb + STG_B + f * APAD + bc16 * 16, Yt + (size_t)f * N_ + bc16 * 8);
    }
    asm volatile("cp.async.commit_group;" ::: "memory");
#pragma unroll
    for (int j = 0; j < 8; ++j) {
        __half2 h0 = __floats2half2_rn(av[j].x, av[j].y);
        __half2 h1 = __floats2half2_rn(av[j].z, av[j].w);
        int r = r0 + 16 * j;
        *reinterpret_cast<uint2*>(smem + STG_A + r * APAD + c4 * 8) =
            make_uint2(*reinterpret_cast<uint32_t*>(&h0), *reinterpret_cast<uint32_t*>(&h1));
    }
    asm volatile("cp.async.wait_group 0;" ::: "memory");
    __syncthreads();

    // ---- main loop ----
    for (int it = 0; it < N_ / KC; ++it) {
        const int cur = it & 1;
        const char* stg = smem + cur * STAGE_SZ;

        if (it < N_ / KC - 1) {
            const int kb = (it + 1) * KC;
#pragma unroll
            for (int j = 0; j < 8; ++j)
                av[j] = *reinterpret_cast<const float4*>(
                    A + (size_t)(r0 + 16 * j) * N_ + kb + c4 * 4);
            const uint32_t nb = sb + (cur ^ 1) * STAGE_SZ;
#pragma unroll
            for (int j = 0; j < 4; ++j) {
                int f = bf0 + 32 * j;
                cp16(nb + STG_B + f * APAD + bc16 * 16, Yt + (size_t)f * N_ + kb + bc16 * 8);
            }
            asm volatile("cp.async.commit_group;" ::: "memory");
        }

        // MMA over current stage
#pragma unroll
        for (int k16 = 0; k16 < 4; ++k16) {
            const int koff = k16 * 32 + t * 4;
            uint32_t af[4][4];
#pragma unroll
            for (int mt = 0; mt < 4; ++mt) {
                int rg = warpM * 64 + mt * 16 + g;
                const char* pA = stg + STG_A + rg * APAD + koff;
                af[mt][0] = *reinterpret_cast<const uint32_t*>(pA);
                af[mt][1] = *reinterpret_cast<const uint32_t*>(pA + 8 * APAD);
                af[mt][2] = *reinterpret_cast<const uint32_t*>(pA + 16);
                af[mt][3] = *reinterpret_cast<const uint32_t*>(pA + 8 * APAD + 16);
            }
            uint32_t bf[4][2];
#pragma unroll
            for (int nt = 0; nt < 4; ++nt) {
                int f = warpC * 32 + nt * 8 + g;
                const char* pB = stg + STG_B + f * APAD + koff;
                bf[nt][0] = *reinterpret_cast<const uint32_t*>(pB);
                bf[nt][1] = *reinterpret_cast<const uint32_t*>(pB + 16);
            }
#pragma unroll
            for (int mt = 0; mt < 4; ++mt)
#pragma unroll
                for (int nt = 0; nt < 4; ++nt)
                    mma_f16(acc[mt][nt], af[mt], bf[nt]);
        }

        if (it < N_ / KC - 1) {
            char* nst = smem + (cur ^ 1) * STAGE_SZ;
#pragma unroll
            for (int j = 0; j < 8; ++j) {
                __half2 h0 = __floats2half2_rn(av[j].x, av[j].y);
                __half2 h1 = __floats2half2_rn(av[j].z, av[j].w);
                int r = r0 + 16 * j;
                *reinterpret_cast<uint2*>(nst + STG_A + r * APAD + c4 * 8) =
                    make_uint2(*reinterpret_cast<uint32_t*>(&h0),
                               *reinterpret_cast<uint32_t*>(&h1));
            }
            asm volatile("cp.async.wait_group 0;" ::: "memory");
        }
        __syncthreads();
    }

    // ---- epilogue: dinv * (acc + y_self) + bias ----
    const float* Yrow = g_y + ((size_t)b * N_ + rowBase) * F_;
    float* Orow = out + ((size_t)b * N_ + rowBase) * F_;
    const float* dv = g_dinv + b * N_ + rowBase;
#pragma unroll
    for (int mt = 0; mt < 4; ++mt) {
        int rl0 = warpM * 64 + mt * 16 + g;
        int rl1 = rl0 + 8;
        float d0 = dv[rl0], d1 = dv[rl1];
#pragma unroll
        for (int nt = 0; nt < 4; ++nt) {
            int c = warpC * 32 + nt * 8 + 2 * t;
            float2 y0 = *reinterpret_cast<const float2*>(Yrow + (size_t)rl0 * F_ + c);
            float2 y1 = *reinterpret_cast<const float2*>(Yrow + (size_t)rl1 * F_ + c);
            float2 bv = *reinterpret_cast<const float2*>(bias + c);
            float2 o0, o1;
            o0.x = d0 * (acc[mt][nt][0] + y0.x) + bv.x;
            o0.y = d0 * (acc[mt][nt][1] + y0.y) + bv.y;
            o1.x = d1 * (acc[mt][nt][2] + y1.x) + bv.x;
            o1.y = d1 * (acc[mt][nt][3] + y1.y) + bv.y;
            *reinterpret_cast<float2*>(Orow + (size_t)rl0 * F_ + c) = o0;
            *reinterpret_cast<float2*>(Orow + (size_t)rl1 * F_ + c) = o1;
        }
    }
}

extern "C" void kernel_launch(void* const* d_in, const int* in_sizes, int n_in,
                              void* d_out, int out_size) {
    const float* x = (const float*)d_in[0];    // [8,2048,128]
    const float* adj = (const float*)d_in[1];  // [8,2048,2048]
    const float* W = (const float*)d_in[2];    // [128,128]
    const float* bias = (const float*)d_in[3]; // [128]
    float* out = (float*)d_out;                // [8,2048,128]

    cudaFuncSetAttribute(spmm_mma, cudaFuncAttributeMaxDynamicSharedMemorySize, K3_SMEM);

    rowsum_kernel<<<B_ * N_, 256>>>(adj);
    xw_kernel<<<(B_ * N_) / 128, 256>>>(x, W);
    spmm_mma<<<dim3(N_ / 128, B_), 256, K3_SMEM>>>(adj, bias, out);
}